// round 1
// baseline (speedup 1.0000x reference)
#include <cuda_runtime.h>
#include <math.h>

// Problem dims
#define Bsz 512
#define Tsz 512
#define Lsz 64
#define Hsz 512
#define H3  1536                // 3*H
#define XW  (Tsz + Lsz - 1)     // 575, width of x per batch row

// ---------------- scratch (static device allocations; no cudaMalloc) -------
__device__ float g_GI1[(size_t)Lsz * Bsz * H3];  // precomputed layer-1 input gates, [L][B][3H] (~201MB)
__device__ float g_GH1[Bsz * H3];
__device__ float g_GI2[Bsz * H3];
__device__ float g_GH2[Bsz * H3];
__device__ float g_H1[Bsz * Hsz];
__device__ float g_H2[Bsz * Hsz];

// ---------------- tiled fp32 NT-GEMM core: C[64 x 64] += A(64xK) * W(64xK)^T + bias
// BM=BN=64, BK=16, 256 threads, 4x4 microtile per thread.
// A: row-major with stride lda (rows are the 64 tile rows)
// W: row-major [N_total][K]; we use rows n0..n0+63
// C: row-major with stride ldc; we write rows 0..63, cols n0..n0+63
__device__ __forceinline__ void gemm_core(
    const float* __restrict__ A, int lda,
    const float* __restrict__ W,
    const float* __restrict__ bias,
    float* __restrict__ C, int ldc,
    int n0, int K)
{
    __shared__ __align__(16) float As[16][64];
    __shared__ __align__(16) float Bs[16][64];

    const int tid = threadIdx.x;        // 0..255
    const int tx = tid & 15;            // 0..15  -> N micro
    const int ty = tid >> 4;            // 0..15  -> M micro

    const int loadRow = tid >> 2;       // 0..63
    const int loadK0  = (tid & 3) * 4;  // 0,4,8,12

    const float* __restrict__ Wp = W + (size_t)n0 * K;

    float acc[4][4];
#pragma unroll
    for (int i = 0; i < 4; i++)
#pragma unroll
        for (int j = 0; j < 4; j++) acc[i][j] = 0.f;

    for (int k0 = 0; k0 < K; k0 += 16) {
        // load A tile (64x16) and W tile (64x16), store k-major in smem
        const float* ap = A + (size_t)loadRow * lda + k0 + loadK0;
        const float* wp = Wp + (size_t)loadRow * K + k0 + loadK0;
#pragma unroll
        for (int i = 0; i < 4; i++) {
            As[loadK0 + i][loadRow] = ap[i];
            Bs[loadK0 + i][loadRow] = wp[i];
        }
        __syncthreads();

#pragma unroll
        for (int k = 0; k < 16; k++) {
            float a[4], b[4];
            *(float4*)a = *(const float4*)&As[k][ty * 4];
            *(float4*)b = *(const float4*)&Bs[k][tx * 4];
#pragma unroll
            for (int i = 0; i < 4; i++)
#pragma unroll
                for (int j = 0; j < 4; j++)
                    acc[i][j] += a[i] * b[j];
        }
        __syncthreads();
    }

#pragma unroll
    for (int i = 0; i < 4; i++) {
        int m = ty * 4 + i;
#pragma unroll
        for (int j = 0; j < 4; j++) {
            int n = n0 + tx * 4 + j;
            C[(size_t)m * ldc + n] = acc[i][j] + bias[n];
        }
    }
}

// ---------------- phase 1: GI1[l][b][:] = x[b, l:l+T] @ W_ih1^T + b_ih1 ----
// grid: (H3/64=24, L*B/64=512), block 256.
// Rows of a 64-row tile share the same l (since 64 | B), so the window view is
// just a strided matrix with lda=XW and base offset l.
__global__ void k_gi1(const float* __restrict__ x,
                      const float* __restrict__ Wih1,
                      const float* __restrict__ bih1)
{
    int m0 = blockIdx.y * 64;         // row in [L*B]
    int l  = m0 >> 9;                 // m0 / B
    int b0 = m0 & (Bsz - 1);          // m0 % B
    const float* A = x + (size_t)b0 * XW + l;
    float* C = g_GI1 + (size_t)m0 * H3;
    gemm_core(A, XW, Wih1, bih1, C, H3, blockIdx.x * 64, Tsz);
}

// ---------------- prologue: GH1 = H1 @ W_hh1^T + b_hh1 ---------------------
__global__ void k_gh1(const float* __restrict__ Whh1,
                      const float* __restrict__ bhh1)
{
    int m0 = blockIdx.y * 64;
    gemm_core(g_H1 + (size_t)m0 * Hsz, Hsz, Whh1, bhh1,
              g_GH1 + (size_t)m0 * H3, H3, blockIdx.x * 64, Hsz);
}

// ---------------- fused 3-GEMM step kernel ---------------------------------
// z=0: GH1(next) = H1_new @ W_hh1^T   (feeds gates1 of t+1)
// z=1: GI2       = H1_new @ W_ih2^T
// z=2: GH2       = H2_old @ W_hh2^T
// grid: (24, 8, 3) = 576 CTAs
__global__ void k_gemm3(const float* __restrict__ Whh1, const float* __restrict__ bhh1,
                        const float* __restrict__ Wih2, const float* __restrict__ bih2,
                        const float* __restrict__ Whh2, const float* __restrict__ bhh2)
{
    const float *A, *W, *bias;
    float* C;
    if (blockIdx.z == 0)      { A = g_H1; W = Whh1; bias = bhh1; C = g_GH1; }
    else if (blockIdx.z == 1) { A = g_H1; W = Wih2; bias = bih2; C = g_GI2; }
    else                      { A = g_H2; W = Whh2; bias = bhh2; C = g_GH2; }
    int m0 = blockIdx.y * 64;
    gemm_core(A + (size_t)m0 * Hsz, Hsz, W, bias,
              C + (size_t)m0 * H3, H3, blockIdx.x * 64, Hsz);
}

__device__ __forceinline__ float sigmoidf_(float v) {
    return 1.f / (1.f + expf(-v));
}

// ---------------- GRU gate elementwise, layer 1 ----------------------------
// grid B, block H
__global__ void k_gates1(int t)
{
    int b = blockIdx.x, j = threadIdx.x;
    const float* gi = g_GI1 + ((size_t)t * Bsz + b) * H3;
    const float* gh = g_GH1 + (size_t)b * H3;
    float r = sigmoidf_(gi[j]           + gh[j]);
    float z = sigmoidf_(gi[Hsz + j]     + gh[Hsz + j]);
    float n = tanhf   (gi[2 * Hsz + j] + r * gh[2 * Hsz + j]);
    size_t hi = (size_t)b * Hsz + j;
    float h = g_H1[hi];
    g_H1[hi] = (1.f - z) * n + z * h;
}

// ---------------- layer 2 gates + fused fc output y[t] ---------------------
// grid B, block H
__global__ void k_gates2(int t,
                         const float* __restrict__ Wfc,
                         const float* __restrict__ bfc,
                         float* __restrict__ out)
{
    __shared__ float red[Hsz];
    int b = blockIdx.x, j = threadIdx.x;
    const float* gi = g_GI2 + (size_t)b * H3;
    const float* gh = g_GH2 + (size_t)b * H3;
    float r = sigmoidf_(gi[j]           + gh[j]);
    float z = sigmoidf_(gi[Hsz + j]     + gh[Hsz + j]);
    float n = tanhf   (gi[2 * Hsz + j] + r * gh[2 * Hsz + j]);
    size_t hi = (size_t)b * Hsz + j;
    float h = g_H2[hi];
    float hnew = (1.f - z) * n + z * h;
    g_H2[hi] = hnew;

    red[j] = hnew * Wfc[j];
    __syncthreads();
#pragma unroll
    for (int s = Hsz / 2; s > 0; s >>= 1) {
        if (j < s) red[j] += red[j + s];
        __syncthreads();
    }
    if (j == 0) out[(size_t)b * Lsz + t] = red[0] + bfc[0];
}

// ---------------- init / copy-out -----------------------------------------
__global__ void k_init(const float* __restrict__ h1in, const float* __restrict__ h2in)
{
    int i = blockIdx.x * blockDim.x + threadIdx.x;
    if (i < Bsz * Hsz) { g_H1[i] = h1in[i]; g_H2[i] = h2in[i]; }
}

__global__ void k_copyout(float* __restrict__ out, int out_size)
{
    int i = blockIdx.x * blockDim.x + threadIdx.x;
    const int yN = Bsz * Lsz, hN = Bsz * Hsz;
    if (yN + 2 * hN <= out_size && i < hN) {
        out[yN + i]      = g_H1[i];
        out[yN + hN + i] = g_H2[i];
    }
}

// ---------------- launch ----------------------------------------------------
extern "C" void kernel_launch(void* const* d_in, const int* in_sizes, int n_in,
                              void* d_out, int out_size)
{
    const float* x    = (const float*)d_in[0];
    const float* h1in = (const float*)d_in[1];
    const float* h2in = (const float*)d_in[2];
    const float* Wih1 = (const float*)d_in[3];
    const float* Whh1 = (const float*)d_in[4];
    const float* bih1 = (const float*)d_in[5];
    const float* bhh1 = (const float*)d_in[6];
    const float* Wih2 = (const float*)d_in[7];
    const float* Whh2 = (const float*)d_in[8];
    const float* bih2 = (const float*)d_in[9];
    const float* bhh2 = (const float*)d_in[10];
    const float* Wfc  = (const float*)d_in[11];
    const float* bfc  = (const float*)d_in[12];
    float* out = (float*)d_out;

    // init hidden states
    k_init<<<(Bsz * Hsz + 255) / 256, 256>>>(h1in, h2in);

    // phase 1: all layer-1 input gates (no recurrence) — fully parallel
    k_gi1<<<dim3(H3 / 64, (Lsz * Bsz) / 64), 256>>>(x, Wih1, bih1);

    // prologue: GH1 for t=0
    k_gh1<<<dim3(H3 / 64, Bsz / 64), 256>>>(Whh1, bhh1);

    for (int t = 0; t < Lsz; t++) {
        k_gates1<<<Bsz, Hsz>>>(t);
        k_gemm3<<<dim3(H3 / 64, Bsz / 64, 3), 256>>>(Whh1, bhh1, Wih2, bih2, Whh2, bhh2);
        k_gates2<<<Bsz, Hsz>>>(t, Wfc, bfc, out);
    }

    k_copyout<<<(Bsz * Hsz + 255) / 256, 256>>>(out, out_size);
}

// round 5
// speedup vs baseline: 2.6364x; 2.6364x over previous
#include <cuda_runtime.h>
#include <cuda_bf16.h>
#include <math.h>
#include <stdint.h>

// Problem dims
#define Bsz 512
#define Tsz 512
#define Lsz 64
#define Hsz 512
#define H3  1536                // 3*H
#define XW  (Tsz + Lsz - 1)     // 575

// ---------------- scratch (__device__ globals; no cudaMalloc) --------------
__device__ float g_GI1[(size_t)Lsz * Bsz * H3];  // [L*B][3H] fp32 (~201MB)
__device__ float g_GH1[Bsz * H3];
__device__ float g_GI2[Bsz * H3];
__device__ float g_GH2[Bsz * H3];
__device__ float g_H1[Bsz * Hsz];
__device__ float g_H2[Bsz * Hsz];

// split-bf16 planes (hi/lo)
__device__ __align__(256) __nv_bfloat16 g_Whh1h[H3 * Hsz], g_Whh1l[H3 * Hsz];
__device__ __align__(256) __nv_bfloat16 g_Wih2h[H3 * Hsz], g_Wih2l[H3 * Hsz];
__device__ __align__(256) __nv_bfloat16 g_Whh2h[H3 * Hsz], g_Whh2l[H3 * Hsz];
__device__ __align__(256) __nv_bfloat16 g_Wih1h[H3 * Hsz], g_Wih1l[H3 * Hsz];
__device__ __align__(256) __nv_bfloat16 g_H1h[Bsz * Hsz], g_H1l[Bsz * Hsz];
__device__ __align__(256) __nv_bfloat16 g_H2h[Bsz * Hsz], g_H2l[Bsz * Hsz];
// windowed x, split planes: [L*B][512]
__device__ __align__(256) __nv_bfloat16 g_Axh[(size_t)Lsz * Bsz * Hsz];
__device__ __align__(256) __nv_bfloat16 g_Axl[(size_t)Lsz * Bsz * Hsz];

// ---------------- helpers ---------------------------------------------------
__device__ __forceinline__ uint32_t smem_u32(const void* p) {
    uint32_t a;
    asm("{ .reg .u64 t; cvta.to.shared.u64 t, %1; cvt.u32.u64 %0, t; }"
        : "=r"(a) : "l"(p));
    return a;
}
__device__ __forceinline__ void cp16(uint32_t dst, const void* src) {
    asm volatile("cp.async.cg.shared.global [%0], [%1], 16;" :: "r"(dst), "l"(src));
}
__device__ __forceinline__ void ldsm4(uint32_t& r0, uint32_t& r1, uint32_t& r2, uint32_t& r3,
                                      uint32_t addr) {
    asm volatile("ldmatrix.sync.aligned.m8n8.x4.shared.b16 {%0,%1,%2,%3}, [%4];"
                 : "=r"(r0), "=r"(r1), "=r"(r2), "=r"(r3) : "r"(addr));
}
__device__ __forceinline__ void mma16816(float* c, const uint32_t* a, const uint32_t* b) {
    asm volatile(
        "mma.sync.aligned.m16n8k16.row.col.f32.bf16.bf16.f32 "
        "{%0,%1,%2,%3}, {%4,%5,%6,%7}, {%8,%9}, {%0,%1,%2,%3};"
        : "+f"(c[0]), "+f"(c[1]), "+f"(c[2]), "+f"(c[3])
        : "r"(a[0]), "r"(a[1]), "r"(a[2]), "r"(a[3]), "r"(b[0]), "r"(b[1]));
}

// smem tile: 128 rows x 32 bf16 (64B data), row stride 80B -> ldmatrix rows hit
// distinct offsets mod 128B (0,80,32,112,64,16,96,48): conflict-free.
#define TROW 80
#define TILE_B (128 * TROW)

// ---------------- split-bf16 GEMM core (mma.sync) ---------------------------
// D[128x128] = sum_{K'=1536} A'(128xK') * B'(128xK')^T + bias
// segments of 512: 0:(Ah,Bh) 1:(Al,Bh) 2:(Ah,Bl); 48 chunks of BK=32.
__device__ __forceinline__ void gemm_mma(
    const __nv_bfloat16* __restrict__ Ah, const __nv_bfloat16* __restrict__ Al, int m0,
    const __nv_bfloat16* __restrict__ Bh, const __nv_bfloat16* __restrict__ Bl, int n0,
    const float* __restrict__ bias, float* __restrict__ C, int ldc)
{
    __shared__ __align__(16) char smA[2][TILE_B];
    __shared__ __align__(16) char smB[2][TILE_B];

    const int tid  = threadIdx.x;
    const int wid  = tid >> 5;
    const int lane = tid & 31;
    const int wm0  = (wid & 1) * 64;   // 2 warps across M
    const int wn0  = (wid >> 1) * 32;  // 4 warps across N

    // loader mapping: 4 threads per row (16B quarters), 64 rows per pass, 2 passes
    const int qrow = tid >> 2;         // 0..63
    const int qk   = tid & 3;          // 16B quarter of the 64B row

    uint32_t sA[2] = { smem_u32(&smA[0][0]), smem_u32(&smA[1][0]) };
    uint32_t sB[2] = { smem_u32(&smB[0][0]), smem_u32(&smB[1][0]) };

    float acc[4][4][4];
#pragma unroll
    for (int mi = 0; mi < 4; mi++)
#pragma unroll
        for (int ni = 0; ni < 4; ni++)
#pragma unroll
            for (int j = 0; j < 4; j++) acc[mi][ni][j] = 0.f;

    auto issue = [&](int c, int buf) {
        const int seg = c >> 4;
        const int kk  = (c & 15) * 32;
        const __nv_bfloat16* As = (seg == 1) ? Al : Ah;
        const __nv_bfloat16* Bs = (seg == 2) ? Bl : Bh;
#pragma unroll
        for (int r = 0; r < 128; r += 64) {
            cp16(sA[buf] + (qrow + r) * TROW + qk * 16,
                 As + (size_t)(m0 + qrow + r) * Hsz + kk + qk * 8);
            cp16(sB[buf] + (qrow + r) * TROW + qk * 16,
                 Bs + (size_t)(n0 + qrow + r) * Hsz + kk + qk * 8);
        }
        asm volatile("cp.async.commit_group;");
    };

    issue(0, 0);
    for (int c = 0; c < 48; c++) {
        const int buf = c & 1;
        if (c + 1 < 48) {
            issue(c + 1, buf ^ 1);
            asm volatile("cp.async.wait_group 1;");
        } else {
            asm volatile("cp.async.wait_group 0;");
        }
        __syncthreads();

#pragma unroll
        for (int kb = 0; kb < 32; kb += 16) {
            uint32_t a[4][4];
#pragma unroll
            for (int mi = 0; mi < 4; mi++) {
                uint32_t addr = sA[buf] + (wm0 + mi * 16 + (lane & 15)) * TROW
                              + (kb + ((lane >> 4) << 3)) * 2;
                ldsm4(a[mi][0], a[mi][1], a[mi][2], a[mi][3], addr);
            }
            uint32_t b[4][2];
#pragma unroll
            for (int nb = 0; nb < 2; nb++) {
                uint32_t addr = sB[buf]
                              + (wn0 + nb * 16 + (lane & 7) + ((lane >> 4) << 3)) * TROW
                              + (kb + ((lane >> 3) & 1) * 8) * 2;
                uint32_t r0, r1, r2, r3;
                ldsm4(r0, r1, r2, r3, addr);
                b[nb * 2][0] = r0;     b[nb * 2][1] = r1;
                b[nb * 2 + 1][0] = r2; b[nb * 2 + 1][1] = r3;
            }
#pragma unroll
            for (int mi = 0; mi < 4; mi++)
#pragma unroll
                for (int ni = 0; ni < 4; ni++)
                    mma16816(acc[mi][ni], a[mi], b[ni]);
        }
        __syncthreads();
    }

    // epilogue: direct fp32 stores + bias (float2 per atom-row)
#pragma unroll
    for (int mi = 0; mi < 4; mi++) {
#pragma unroll
        for (int ni = 0; ni < 4; ni++) {
            int r   = m0 + wm0 + mi * 16 + (lane >> 2);
            int cix = n0 + wn0 + ni * 8 + (lane & 3) * 2;
            float b0 = bias[cix], b1 = bias[cix + 1];
            *(float2*)&C[(size_t)r * ldc + cix] =
                make_float2(acc[mi][ni][0] + b0, acc[mi][ni][1] + b1);
            *(float2*)&C[(size_t)(r + 8) * ldc + cix] =
                make_float2(acc[mi][ni][2] + b0, acc[mi][ni][3] + b1);
        }
    }
}

// ---------------- GEMM wrappers --------------------------------------------
__global__ void __launch_bounds__(256, 1)
k_gi1_tc(const float* __restrict__ bih1)
{
    gemm_mma(g_Axh, g_Axl, blockIdx.y * 128,
             g_Wih1h, g_Wih1l, blockIdx.x * 128,
             bih1, g_GI1, H3);
}

__global__ void __launch_bounds__(256, 1)
k_gh1_tc(const float* __restrict__ bhh1)
{
    gemm_mma(g_H1h, g_H1l, blockIdx.y * 128,
             g_Whh1h, g_Whh1l, blockIdx.x * 128,
             bhh1, g_GH1, H3);
}

// per-step fused 3-GEMM: grid (12, 4, 3)
__global__ void __launch_bounds__(256, 1)
k_gemm3_tc(const float* __restrict__ bhh1, const float* __restrict__ bih2,
           const float* __restrict__ bhh2)
{
    const __nv_bfloat16 *Ah, *Al, *Bh, *Bl;
    const float* bias;
    float* C;
    if (blockIdx.z == 0)      { Ah = g_H1h; Al = g_H1l; Bh = g_Whh1h; Bl = g_Whh1l; bias = bhh1; C = g_GH1; }
    else if (blockIdx.z == 1) { Ah = g_H1h; Al = g_H1l; Bh = g_Wih2h; Bl = g_Wih2l; bias = bih2; C = g_GI2; }
    else                      { Ah = g_H2h; Al = g_H2l; Bh = g_Whh2h; Bl = g_Whh2l; bias = bhh2; C = g_GH2; }
    gemm_mma(Ah, Al, blockIdx.y * 128, Bh, Bl, blockIdx.x * 128, bias, C, H3);
}

// ---------------- elementwise ----------------------------------------------
__device__ __forceinline__ float sigmoidf_(float v) {
    return 1.f / (1.f + __expf(-v));
}
__device__ __forceinline__ void split_store(float v, __nv_bfloat16* hp, __nv_bfloat16* lp, size_t i) {
    __nv_bfloat16 h = __float2bfloat16(v);
    hp[i] = h;
    lp[i] = __float2bfloat16(v - __bfloat162float(h));
}

__global__ void k_gates1(int t)
{
    int b = blockIdx.x, j = threadIdx.x;
    const float* gi = g_GI1 + ((size_t)t * Bsz + b) * H3;
    const float* gh = g_GH1 + (size_t)b * H3;
    float r = sigmoidf_(gi[j]           + gh[j]);
    float z = sigmoidf_(gi[Hsz + j]     + gh[Hsz + j]);
    float n = tanhf   (gi[2 * Hsz + j] + r * gh[2 * Hsz + j]);
    size_t hi = (size_t)b * Hsz + j;
    float h = g_H1[hi];
    float hnew = (1.f - z) * n + z * h;
    g_H1[hi] = hnew;
    split_store(hnew, g_H1h, g_H1l, hi);
}

// fused: layer-2 gates + fc output for step t, then layer-1 gates for step t+1
__global__ void k_gates12(int t, const float* __restrict__ Wfc,
                          const float* __restrict__ bfc, float* __restrict__ out)
{
    __shared__ float red[Hsz];
    int b = blockIdx.x, j = threadIdx.x;
    size_t hi = (size_t)b * Hsz + j;

    // ---- layer 2 gates + y(t)
    {
        const float* gi = g_GI2 + (size_t)b * H3;
        const float* gh = g_GH2 + (size_t)b * H3;
        float r = sigmoidf_(gi[j]           + gh[j]);
        float z = sigmoidf_(gi[Hsz + j]     + gh[Hsz + j]);
        float n = tanhf   (gi[2 * Hsz + j] + r * gh[2 * Hsz + j]);
        float h = g_H2[hi];
        float hnew = (1.f - z) * n + z * h;
        g_H2[hi] = hnew;
        split_store(hnew, g_H2h, g_H2l, hi);
        red[j] = hnew * Wfc[j];
    }
    __syncthreads();
#pragma unroll
    for (int s = Hsz / 2; s > 0; s >>= 1) {
        if (j < s) red[j] += red[j + s];
        __syncthreads();
    }
    if (j == 0) out[(size_t)b * Lsz + t] = red[0] + bfc[0];

    // ---- layer 1 gates for step t+1 (GH1 was refreshed by this step's gemm3)
    if (t + 1 < Lsz) {
        const float* gi = g_GI1 + ((size_t)(t + 1) * Bsz + b) * H3;
        const float* gh = g_GH1 + (size_t)b * H3;
        float r = sigmoidf_(gi[j]           + gh[j]);
        float z = sigmoidf_(gi[Hsz + j]     + gh[Hsz + j]);
        float n = tanhf   (gi[2 * Hsz + j] + r * gh[2 * Hsz + j]);
        float h = g_H1[hi];
        float hnew = (1.f - z) * n + z * h;
        g_H1[hi] = hnew;
        split_store(hnew, g_H1h, g_H1l, hi);
    }
}

// ---------------- conversions ----------------------------------------------
__global__ void k_split_w(const float* __restrict__ Whh1, const float* __restrict__ Wih2,
                          const float* __restrict__ Whh2, const float* __restrict__ Wih1)
{
    int i = blockIdx.x * blockDim.x + threadIdx.x;
    if (i >= H3 * Hsz) return;
    split_store(Whh1[i], g_Whh1h, g_Whh1l, i);
    split_store(Wih2[i], g_Wih2h, g_Wih2l, i);
    split_store(Whh2[i], g_Whh2h, g_Whh2l, i);
    split_store(Wih1[i], g_Wih1h, g_Wih1l, i);
}

__global__ void k_convx(const float* __restrict__ x)
{
    long long i = blockIdx.x * (long long)blockDim.x + threadIdx.x;
    if (i >= (long long)Lsz * Bsz * Hsz) return;
    int k   = (int)(i & 511);
    int rem = (int)(i >> 9);
    int b   = rem & 511;
    int l   = rem >> 9;
    float v = x[(size_t)b * XW + l + k];
    split_store(v, g_Axh, g_Axl, (size_t)i);
}

__global__ void k_init(const float* __restrict__ h1in, const float* __restrict__ h2in)
{
    int i = blockIdx.x * blockDim.x + threadIdx.x;
    if (i < Bsz * Hsz) {
        float v1 = h1in[i], v2 = h2in[i];
        g_H1[i] = v1; g_H2[i] = v2;
        split_store(v1, g_H1h, g_H1l, i);
        split_store(v2, g_H2h, g_H2l, i);
    }
}

__global__ void k_copyout(float* __restrict__ out, int out_size)
{
    int i = blockIdx.x * blockDim.x + threadIdx.x;
    const int yN = Bsz * Lsz, hN = Bsz * Hsz;
    if (yN + 2 * hN <= out_size && i < hN) {
        out[yN + i]      = g_H1[i];
        out[yN + hN + i] = g_H2[i];
    }
}

// ---------------- launch ----------------------------------------------------
extern "C" void kernel_launch(void* const* d_in, const int* in_sizes, int n_in,
                              void* d_out, int out_size)
{
    const float* x    = (const float*)d_in[0];
    const float* h1in = (const float*)d_in[1];
    const float* h2in = (const float*)d_in[2];
    const float* Wih1 = (const float*)d_in[3];
    const float* Whh1 = (const float*)d_in[4];
    const float* bih1 = (const float*)d_in[5];
    const float* bhh1 = (const float*)d_in[6];
    const float* Wih2 = (const float*)d_in[7];
    const float* Whh2 = (const float*)d_in[8];
    const float* bih2 = (const float*)d_in[9];
    const float* bhh2 = (const float*)d_in[10];
    const float* Wfc  = (const float*)d_in[11];
    const float* bfc  = (const float*)d_in[12];
    float* out = (float*)d_out;

    k_init<<<(Bsz * Hsz + 255) / 256, 256>>>(h1in, h2in);
    k_split_w<<<(H3 * Hsz + 255) / 256, 256>>>(Whh1, Wih2, Whh2, Wih1);
    k_convx<<<(int)(((long long)Lsz * Bsz * Hsz + 255) / 256), 256>>>(x);

    // phase 1: all layer-1 input gates (parallel, tensor pipe)
    k_gi1_tc<<<dim3(H3 / 128, (Lsz * Bsz) / 128), 256>>>(bih1);

    // prologue: GH1 for t=0, then gates1(0)
    k_gh1_tc<<<dim3(H3 / 128, Bsz / 128), 256>>>(bhh1);
    k_gates1<<<Bsz, Hsz>>>(0);

    for (int t = 0; t < Lsz; t++) {
        // z=0: GH1(t+1) = H1 @ Whh1^T ; z=1: GI2 = H1 @ Wih2^T ; z=2: GH2 = H2 @ Whh2^T
        k_gemm3_tc<<<dim3(H3 / 128, Bsz / 128, 3), 256>>>(bhh1, bih2, bhh2);
        k_gates12<<<Bsz, Hsz>>>(t, Wfc, bfc, out);
    }

    k_copyout<<<(Bsz * Hsz + 255) / 256, 256>>>(out, out_size);
}

// round 6
// speedup vs baseline: 3.2621x; 1.2373x over previous
#include <cuda_runtime.h>
#include <cuda_bf16.h>
#include <math.h>
#include <stdint.h>

// Problem dims
#define Bsz 512
#define Tsz 512
#define Lsz 64
#define Hsz 512
#define H3  1536                // 3*H
#define XW  (Tsz + Lsz - 1)     // 575

// ---------------- scratch (__device__ globals; no cudaMalloc) --------------
__device__ float g_GI1[(size_t)Lsz * Bsz * H3];  // [L*B][3H] fp32 (~201MB)
__device__ float g_GH1[Bsz * H3];
__device__ float g_GI2[Bsz * H3];
__device__ float g_GH2[Bsz * H3];
__device__ float g_H1[Bsz * Hsz];
__device__ float g_H2[Bsz * Hsz];

// split-bf16 planes (hi/lo)
__device__ __align__(256) __nv_bfloat16 g_Whh1h[H3 * Hsz], g_Whh1l[H3 * Hsz];
__device__ __align__(256) __nv_bfloat16 g_Wih2h[H3 * Hsz], g_Wih2l[H3 * Hsz];
__device__ __align__(256) __nv_bfloat16 g_Whh2h[H3 * Hsz], g_Whh2l[H3 * Hsz];
__device__ __align__(256) __nv_bfloat16 g_Wih1h[H3 * Hsz], g_Wih1l[H3 * Hsz];
__device__ __align__(256) __nv_bfloat16 g_H1h[Bsz * Hsz], g_H1l[Bsz * Hsz];
__device__ __align__(256) __nv_bfloat16 g_H2h[Bsz * Hsz], g_H2l[Bsz * Hsz];
// windowed x, split planes: [L*B][512]
__device__ __align__(256) __nv_bfloat16 g_Axh[(size_t)Lsz * Bsz * Hsz];
__device__ __align__(256) __nv_bfloat16 g_Axl[(size_t)Lsz * Bsz * Hsz];

// ---------------- helpers ---------------------------------------------------
__device__ __forceinline__ uint32_t smem_u32(const void* p) {
    uint32_t a;
    asm("{ .reg .u64 t; cvta.to.shared.u64 t, %1; cvt.u32.u64 %0, t; }"
        : "=r"(a) : "l"(p));
    return a;
}
__device__ __forceinline__ void cp16(uint32_t dst, const void* src) {
    asm volatile("cp.async.cg.shared.global [%0], [%1], 16;" :: "r"(dst), "l"(src));
}
__device__ __forceinline__ void ldsm4(uint32_t& r0, uint32_t& r1, uint32_t& r2, uint32_t& r3,
                                      uint32_t addr) {
    asm volatile("ldmatrix.sync.aligned.m8n8.x4.shared.b16 {%0,%1,%2,%3}, [%4];"
                 : "=r"(r0), "=r"(r1), "=r"(r2), "=r"(r3) : "r"(addr));
}
__device__ __forceinline__ void mma16816(float* c, const uint32_t* a, const uint32_t* b) {
    asm volatile(
        "mma.sync.aligned.m16n8k16.row.col.f32.bf16.bf16.f32 "
        "{%0,%1,%2,%3}, {%4,%5,%6,%7}, {%8,%9}, {%0,%1,%2,%3};"
        : "+f"(c[0]), "+f"(c[1]), "+f"(c[2]), "+f"(c[3])
        : "r"(a[0]), "r"(a[1]), "r"(a[2]), "r"(a[3]), "r"(b[0]), "r"(b[1]));
}

// smem tile row: 32 bf16 (64B data), stride 80B -> ldmatrix conflict-free.
#define TROW   80
#define STAGES 3
#define BTILE  (128 * TROW)

// ---------------- split-bf16 GEMM core (mma.sync, 3-stage pipeline) ---------
// D[TM x 128] = sum_{K'=1536} A'(TM x K') * B'(128 x K')^T + bias
// segments of 512: 0:(Ah,Bh) 1:(Al,Bh) 2:(Ah,Bl); 48 chunks of BK=32.
template<int TM>
__device__ __forceinline__ void gemm_mma(
    const __nv_bfloat16* __restrict__ Ah, const __nv_bfloat16* __restrict__ Al, int m0,
    const __nv_bfloat16* __restrict__ Bh, const __nv_bfloat16* __restrict__ Bl, int n0,
    const float* __restrict__ bias, float* __restrict__ C, int ldc)
{
    extern __shared__ __align__(16) char smraw[];
    constexpr int ATILE = TM * TROW;
    constexpr int MA    = TM / 32;          // 16-row M atoms per warp
    const uint32_t sA = smem_u32(smraw);
    const uint32_t sB = sA + STAGES * ATILE;

    const int tid  = threadIdx.x;
    const int wid  = tid >> 5;
    const int lane = tid & 31;
    const int wm0  = (wid & 1) * (TM / 2);  // 2 warps across M
    const int wn0  = (wid >> 1) * 32;       // 4 warps across N

    // loader mapping: 4 threads per row (16B quarters), 64 rows per pass
    const int qrow = tid >> 2;              // 0..63
    const int qk   = tid & 3;

    float acc[MA][4][4];
#pragma unroll
    for (int mi = 0; mi < MA; mi++)
#pragma unroll
        for (int ni = 0; ni < 4; ni++)
#pragma unroll
            for (int j = 0; j < 4; j++) acc[mi][ni][j] = 0.f;

    auto issue = [&](int c, int st) {
        const int seg = c >> 4;
        const int kk  = (c & 15) * 32;
        const __nv_bfloat16* As = (seg == 1) ? Al : Ah;
        const __nv_bfloat16* Bs = (seg == 2) ? Bl : Bh;
#pragma unroll
        for (int r = 0; r < TM; r += 64)
            cp16(sA + st * ATILE + (qrow + r) * TROW + qk * 16,
                 As + (size_t)(m0 + qrow + r) * Hsz + kk + qk * 8);
#pragma unroll
        for (int r = 0; r < 128; r += 64)
            cp16(sB + st * BTILE + (qrow + r) * TROW + qk * 16,
                 Bs + (size_t)(n0 + qrow + r) * Hsz + kk + qk * 8);
        asm volatile("cp.async.commit_group;");
    };

    issue(0, 0);
    issue(1, 1);

    for (int c = 0; c < 48; c++) {
        const int st = c % STAGES;
        if (c < 47) asm volatile("cp.async.wait_group 1;");
        else        asm volatile("cp.async.wait_group 0;");
        __syncthreads();

        // prefetch chunk c+2 while computing chunk c (its buffer was last read
        // at chunk c-1; the barrier above orders that read before this write)
        if (c + 2 < 48) issue(c + 2, (c + 2) % STAGES);

        const uint32_t bufA = sA + st * ATILE;
        const uint32_t bufB = sB + st * BTILE;
#pragma unroll
        for (int kb = 0; kb < 32; kb += 16) {
            uint32_t a[MA][4];
#pragma unroll
            for (int mi = 0; mi < MA; mi++) {
                uint32_t addr = bufA + (wm0 + mi * 16 + (lane & 15)) * TROW
                              + (kb + ((lane >> 4) << 3)) * 2;
                ldsm4(a[mi][0], a[mi][1], a[mi][2], a[mi][3], addr);
            }
            uint32_t b[4][2];
#pragma unroll
            for (int nb = 0; nb < 2; nb++) {
                uint32_t addr = bufB
                              + (wn0 + nb * 16 + (lane & 7) + ((lane >> 4) << 3)) * TROW
                              + (kb + ((lane >> 3) & 1) * 8) * 2;
                uint32_t r0, r1, r2, r3;
                ldsm4(r0, r1, r2, r3, addr);
                b[nb * 2][0] = r0;     b[nb * 2][1] = r1;
                b[nb * 2 + 1][0] = r2; b[nb * 2 + 1][1] = r3;
            }
#pragma unroll
            for (int mi = 0; mi < MA; mi++)
#pragma unroll
                for (int ni = 0; ni < 4; ni++)
                    mma16816(acc[mi][ni], a[mi], b[ni]);
        }
    }

    // epilogue: direct fp32 stores + bias
#pragma unroll
    for (int mi = 0; mi < MA; mi++) {
#pragma unroll
        for (int ni = 0; ni < 4; ni++) {
            int r   = m0 + wm0 + mi * 16 + (lane >> 2);
            int cix = n0 + wn0 + ni * 8 + (lane & 3) * 2;
            float b0 = bias[cix], b1 = bias[cix + 1];
            *(float2*)&C[(size_t)r * ldc + cix] =
                make_float2(acc[mi][ni][0] + b0, acc[mi][ni][1] + b1);
            *(float2*)&C[(size_t)(r + 8) * ldc + cix] =
                make_float2(acc[mi][ni][2] + b0, acc[mi][ni][3] + b1);
        }
    }
}

#define SMEM128 (STAGES * (128 * TROW) * 2)            // 61440
#define SMEM64  (STAGES * ((64 * TROW) + (128 * TROW)))// 46080

// ---------------- GEMM wrappers --------------------------------------------
__global__ void __launch_bounds__(256, 2)
k_gi1_tc(const float* __restrict__ bih1)
{
    gemm_mma<128>(g_Axh, g_Axl, blockIdx.y * 128,
                  g_Wih1h, g_Wih1l, blockIdx.x * 128,
                  bih1, g_GI1, H3);
}

__global__ void __launch_bounds__(256, 2)
k_gh1_tc(const float* __restrict__ bhh1)
{
    gemm_mma<128>(g_H1h, g_H1l, blockIdx.y * 128,
                  g_Whh1h, g_Whh1l, blockIdx.x * 128,
                  bhh1, g_GH1, H3);
}

// per-step fused 3-GEMM, 64x128 tiles: grid (12, 8, 3) = 288 CTAs (2/SM)
__global__ void __launch_bounds__(256, 2)
k_gemm3_tc(const float* __restrict__ bhh1, const float* __restrict__ bih2,
           const float* __restrict__ bhh2)
{
    const __nv_bfloat16 *Ah, *Al, *Bh, *Bl;
    const float* bias;
    float* C;
    if (blockIdx.z == 0)      { Ah = g_H1h; Al = g_H1l; Bh = g_Whh1h; Bl = g_Whh1l; bias = bhh1; C = g_GH1; }
    else if (blockIdx.z == 1) { Ah = g_H1h; Al = g_H1l; Bh = g_Wih2h; Bl = g_Wih2l; bias = bih2; C = g_GI2; }
    else                      { Ah = g_H2h; Al = g_H2l; Bh = g_Whh2h; Bl = g_Whh2l; bias = bhh2; C = g_GH2; }
    gemm_mma<64>(Ah, Al, blockIdx.y * 64, Bh, Bl, blockIdx.x * 128, bias, C, H3);
}

// ---------------- elementwise ----------------------------------------------
__device__ __forceinline__ float sigmoidf_(float v) {
    return 1.f / (1.f + __expf(-v));
}
__device__ __forceinline__ void split_store(float v, __nv_bfloat16* hp, __nv_bfloat16* lp, size_t i) {
    __nv_bfloat16 h = __float2bfloat16(v);
    hp[i] = h;
    lp[i] = __float2bfloat16(v - __bfloat162float(h));
}

__global__ void k_gates1(int t)
{
    int b = blockIdx.x, j = threadIdx.x;
    const float* gi = g_GI1 + ((size_t)t * Bsz + b) * H3;
    const float* gh = g_GH1 + (size_t)b * H3;
    float r = sigmoidf_(gi[j]           + gh[j]);
    float z = sigmoidf_(gi[Hsz + j]     + gh[Hsz + j]);
    float n = tanhf   (gi[2 * Hsz + j] + r * gh[2 * Hsz + j]);
    size_t hi = (size_t)b * Hsz + j;
    float h = g_H1[hi];
    float hnew = (1.f - z) * n + z * h;
    g_H1[hi] = hnew;
    split_store(hnew, g_H1h, g_H1l, hi);
}

// fused: layer-2 gates + fc output for step t, then layer-1 gates for step t+1
__global__ void k_gates12(int t, const float* __restrict__ Wfc,
                          const float* __restrict__ bfc, float* __restrict__ out)
{
    __shared__ float red[16];
    int b = blockIdx.x, j = threadIdx.x;
    int lane = j & 31, wid = j >> 5;
    size_t hi = (size_t)b * Hsz + j;

    // ---- layer 2 gates + y(t)
    {
        const float* gi = g_GI2 + (size_t)b * H3;
        const float* gh = g_GH2 + (size_t)b * H3;
        float r = sigmoidf_(gi[j]           + gh[j]);
        float z = sigmoidf_(gi[Hsz + j]     + gh[Hsz + j]);
        float n = tanhf   (gi[2 * Hsz + j] + r * gh[2 * Hsz + j]);
        float h = g_H2[hi];
        float hnew = (1.f - z) * n + z * h;
        g_H2[hi] = hnew;
        split_store(hnew, g_H2h, g_H2l, hi);

        float v = hnew * Wfc[j];
#pragma unroll
        for (int s = 16; s > 0; s >>= 1) v += __shfl_down_sync(0xffffffffu, v, s);
        if (lane == 0) red[wid] = v;
    }
    __syncthreads();
    if (wid == 0) {
        float v = (lane < 16) ? red[lane] : 0.f;
#pragma unroll
        for (int s = 8; s > 0; s >>= 1) v += __shfl_down_sync(0xffffffffu, v, s);
        if (lane == 0) out[(size_t)b * Lsz + t] = v + bfc[0];
    }

    // ---- layer 1 gates for step t+1 (GH1 was refreshed by this step's gemm3)
    if (t + 1 < Lsz) {
        const float* gi = g_GI1 + ((size_t)(t + 1) * Bsz + b) * H3;
        const float* gh = g_GH1 + (size_t)b * H3;
        float r = sigmoidf_(gi[j]           + gh[j]);
        float z = sigmoidf_(gi[Hsz + j]     + gh[Hsz + j]);
        float n = tanhf   (gi[2 * Hsz + j] + r * gh[2 * Hsz + j]);
        float h = g_H1[hi];
        float hnew = (1.f - z) * n + z * h;
        g_H1[hi] = hnew;
        split_store(hnew, g_H1h, g_H1l, hi);
    }
}

// ---------------- conversions ----------------------------------------------
__global__ void k_split_w(const float* __restrict__ Whh1, const float* __restrict__ Wih2,
                          const float* __restrict__ Whh2, const float* __restrict__ Wih1)
{
    int i = blockIdx.x * blockDim.x + threadIdx.x;
    if (i >= H3 * Hsz) return;
    split_store(Whh1[i], g_Whh1h, g_Whh1l, i);
    split_store(Wih2[i], g_Wih2h, g_Wih2l, i);
    split_store(Whh2[i], g_Whh2h, g_Whh2l, i);
    split_store(Wih1[i], g_Wih1h, g_Wih1l, i);
}

__global__ void k_convx(const float* __restrict__ x)
{
    long long i = blockIdx.x * (long long)blockDim.x + threadIdx.x;
    if (i >= (long long)Lsz * Bsz * Hsz) return;
    int k   = (int)(i & 511);
    int rem = (int)(i >> 9);
    int b   = rem & 511;
    int l   = rem >> 9;
    float v = x[(size_t)b * XW + l + k];
    split_store(v, g_Axh, g_Axl, (size_t)i);
}

__global__ void k_init(const float* __restrict__ h1in, const float* __restrict__ h2in)
{
    int i = blockIdx.x * blockDim.x + threadIdx.x;
    if (i < Bsz * Hsz) {
        float v1 = h1in[i], v2 = h2in[i];
        g_H1[i] = v1; g_H2[i] = v2;
        split_store(v1, g_H1h, g_H1l, i);
        split_store(v2, g_H2h, g_H2l, i);
    }
}

__global__ void k_copyout(float* __restrict__ out, int out_size)
{
    int i = blockIdx.x * blockDim.x + threadIdx.x;
    const int yN = Bsz * Lsz, hN = Bsz * Hsz;
    if (yN + 2 * hN <= out_size && i < hN) {
        out[yN + i]      = g_H1[i];
        out[yN + hN + i] = g_H2[i];
    }
}

// ---------------- launch ----------------------------------------------------
extern "C" void kernel_launch(void* const* d_in, const int* in_sizes, int n_in,
                              void* d_out, int out_size)
{
    const float* x    = (const float*)d_in[0];
    const float* h1in = (const float*)d_in[1];
    const float* h2in = (const float*)d_in[2];
    const float* Wih1 = (const float*)d_in[3];
    const float* Whh1 = (const float*)d_in[4];
    const float* bih1 = (const float*)d_in[5];
    const float* bhh1 = (const float*)d_in[6];
    const float* Wih2 = (const float*)d_in[7];
    const float* Whh2 = (const float*)d_in[8];
    const float* bih2 = (const float*)d_in[9];
    const float* bhh2 = (const float*)d_in[10];
    const float* Wfc  = (const float*)d_in[11];
    const float* bfc  = (const float*)d_in[12];
    float* out = (float*)d_out;

    cudaFuncSetAttribute(k_gi1_tc,   cudaFuncAttributeMaxDynamicSharedMemorySize, SMEM128);
    cudaFuncSetAttribute(k_gh1_tc,   cudaFuncAttributeMaxDynamicSharedMemorySize, SMEM128);
    cudaFuncSetAttribute(k_gemm3_tc, cudaFuncAttributeMaxDynamicSharedMemorySize, SMEM64);

    k_init<<<(Bsz * Hsz + 255) / 256, 256>>>(h1in, h2in);
    k_split_w<<<(H3 * Hsz + 255) / 256, 256>>>(Whh1, Wih2, Whh2, Wih1);
    k_convx<<<(int)(((long long)Lsz * Bsz * Hsz + 255) / 256), 256>>>(x);

    // phase 1: all layer-1 input gates (parallel, tensor pipe)
    k_gi1_tc<<<dim3(H3 / 128, (Lsz * Bsz) / 128), 256, SMEM128>>>(bih1);

    // prologue: GH1 for t=0, then gates1(0)
    k_gh1_tc<<<dim3(H3 / 128, Bsz / 128), 256, SMEM128>>>(bhh1);
    k_gates1<<<Bsz, Hsz>>>(0);

    for (int t = 0; t < Lsz; t++) {
        // z=0: GH1(t+1) = H1 @ Whh1^T ; z=1: GI2 = H1 @ Wih2^T ; z=2: GH2 = H2 @ Whh2^T
        k_gemm3_tc<<<dim3(H3 / 128, Bsz / 64, 3), 256, SMEM64>>>(bhh1, bih2, bhh2);
        k_gates12<<<Bsz, Hsz>>>(t, Wfc, bfc, out);
    }

    k_copyout<<<(Bsz * Hsz + 255) / 256, 256>>>(out, out_size);
}